// round 2
// baseline (speedup 1.0000x reference)
#include <cuda_runtime.h>
#include <cstdint>

// ChebConv K=8: decode edges (dtype-robust), build CSR by dst, 7 SpMM
// propagations (128-dim), then one fused GEMM [50000,1024]x[1024,64]
// with bias+ReLU epilogue.

#define N_NODES 50000
#define N_EDGES 800000
#define F_IN    128
#define F_OUT   64
#define KORD    8
#define KTOT    (KORD * F_IN)   // 1024

// ---- scratch (static device globals; no allocations) ----
__device__ __align__(16) float g_Tall[(size_t)N_NODES * KTOT]; // T_k in column slot k*128
__device__ int   g_is64;                           // edge_index dtype flag
__device__ int   g_src[N_EDGES];
__device__ int   g_dst[N_EDGES];
__device__ int   g_cnt[N_NODES];                   // in-degree (by dst)
__device__ int   g_deg[N_NODES];                   // out-degree (by src)
__device__ float g_dis[N_NODES];                   // deg^{-1/2} (0 if deg==0)
__device__ int   g_rowptr[N_NODES + 1];
__device__ int   g_cursor[N_NODES];
__device__ int   g_esrc[N_EDGES];
__device__ float g_ew[N_EDGES];

// ---------------------------------------------------------------------------
__global__ void detect_kernel(const unsigned int* __restrict__ p) {
    // int64 node ids < 50000 => high 32-bit word of each element is 0.
    // int32 buffer => odd words are node ids (vanishingly unlikely all zero).
    if (threadIdx.x == 0 && blockIdx.x == 0) {
        int is64 = 1;
        for (int i = 0; i < 256; i++) {
            if (p[2 * i + 1] != 0u) { is64 = 0; break; }
        }
        g_is64 = is64;
    }
}

__global__ void zero_kernel() {
    int i = blockIdx.x * blockDim.x + threadIdx.x;
    if (i < N_NODES) { g_cnt[i] = 0; g_deg[i] = 0; }
}

// decode edge list (int32 or int64) + degree histograms
__global__ void decode_hist_kernel(const void* __restrict__ ei) {
    int e = blockIdx.x * blockDim.x + threadIdx.x;
    if (e < N_EDGES) {
        int s, d;
        if (g_is64) {
            const long long* p = (const long long*)ei;
            s = (int)p[e];
            d = (int)p[N_EDGES + e];
        } else {
            const int* p = (const int*)ei;
            s = p[e];
            d = p[N_EDGES + e];
        }
        s = min(max(s, 0), N_NODES - 1);
        d = min(max(d, 0), N_NODES - 1);
        g_src[e] = s;
        g_dst[e] = d;
        atomicAdd(&g_deg[s], 1);
        atomicAdd(&g_cnt[d], 1);
    }
}

__global__ void dis_kernel() {
    int i = blockIdx.x * blockDim.x + threadIdx.x;
    if (i < N_NODES) {
        int d = g_deg[i];
        g_dis[i] = (d > 0) ? rsqrtf((float)d) : 0.0f;
    }
}

// single-block exclusive scan of g_cnt -> g_rowptr (+ copy to g_cursor)
__global__ void scan_kernel() {
    __shared__ int sh[1024];
    __shared__ int s_carry;
    if (threadIdx.x == 0) s_carry = 0;
    __syncthreads();
    for (int base = 0; base < N_NODES; base += 1024) {
        int i = base + (int)threadIdx.x;
        int v = (i < N_NODES) ? g_cnt[i] : 0;
        sh[threadIdx.x] = v;
        __syncthreads();
        #pragma unroll
        for (int off = 1; off < 1024; off <<= 1) {
            int t = (threadIdx.x >= off) ? sh[threadIdx.x - off] : 0;
            __syncthreads();
            sh[threadIdx.x] += t;
            __syncthreads();
        }
        int inc  = sh[threadIdx.x];
        int excl = s_carry + inc - v;
        if (i < N_NODES) { g_rowptr[i] = excl; g_cursor[i] = excl; }
        __syncthreads();
        if (threadIdx.x == 1023) s_carry += inc;
        __syncthreads();
    }
    if (threadIdx.x == 0) g_rowptr[N_NODES] = s_carry;
}

__global__ void scatter_kernel() {
    int e = blockIdx.x * blockDim.x + threadIdx.x;
    if (e < N_EDGES) {
        int s = g_src[e];
        int d = g_dst[e];
        float w = -g_dis[s] * g_dis[d];
        int pos = atomicAdd(&g_cursor[d], 1);
        g_esrc[pos] = s;
        g_ew[pos]   = w;
    }
}

__global__ void copyx_kernel(const float* __restrict__ x) {
    int i = blockIdx.x * blockDim.x + threadIdx.x;
    if (i < N_NODES * F_IN) {
        int row = i >> 7;          // / 128
        int col = i & (F_IN - 1);  // % 128
        g_Tall[(size_t)row * KTOT + col] = x[i];
    }
}

// one dst node per block; 128 threads = 128 feature columns.
// mode 0: T_out = prop(T_in)
// mode 1: T_out = 2*prop(T_in) - T_prev
__global__ void spmm_kernel(int slot_in, int slot_prev, int slot_out, int mode) {
    int n   = blockIdx.x;
    int tid = threadIdx.x;
    int beg = g_rowptr[n];
    int end = g_rowptr[n + 1];
    float acc = 0.0f;
    int cin = slot_in * F_IN;
    #pragma unroll 4
    for (int e = beg; e < end; ++e) {
        int   s = __ldg(&g_esrc[e]);
        float w = __ldg(&g_ew[e]);
        acc += w * __ldg(&g_Tall[(size_t)s * KTOT + cin + tid]);
    }
    size_t orow = (size_t)n * KTOT;
    float r;
    if (mode) r = 2.0f * acc - g_Tall[orow + slot_prev * F_IN + tid];
    else      r = acc;
    g_Tall[orow + slot_out * F_IN + tid] = r;
}

// out[50000,64] = relu(Tall[50000,1024] @ W[1024,64] + b), 64x64 tile, 128 threads
__global__ void gemm_kernel(const float* __restrict__ W, const float* __restrict__ b,
                            float* __restrict__ out) {
    __shared__ float As[32][65];   // [kk][m], padded
    __shared__ float Ws[32][64];   // [kk][n]
    int tid  = threadIdx.x;        // 0..127
    int row0 = blockIdx.x * 64;
    int rowg = tid >> 3;           // 0..15 -> 4 rows each
    int colg = tid & 7;            // 0..7  -> 8 cols each
    float acc[4][8];
    #pragma unroll
    for (int i = 0; i < 4; i++)
        #pragma unroll
        for (int j = 0; j < 8; j++) acc[i][j] = 0.0f;

    for (int kt = 0; kt < KTOT; kt += 32) {
        // load A tile (64 rows x 32 k) as float4 along k, store transposed
        #pragma unroll
        for (int r = 0; r < 4; r++) {
            int i  = tid + 128 * r;     // 0..511
            int m  = i >> 3;            // 0..63
            int kq = i & 7;             // 0..7 (float4 index within 32 k)
            int grow = row0 + m;
            float4 v = make_float4(0.f, 0.f, 0.f, 0.f);
            if (grow < N_NODES)
                v = *(const float4*)&g_Tall[(size_t)grow * KTOT + kt + kq * 4];
            As[kq * 4 + 0][m] = v.x;
            As[kq * 4 + 1][m] = v.y;
            As[kq * 4 + 2][m] = v.z;
            As[kq * 4 + 3][m] = v.w;
        }
        // load W tile (32 k x 64 n)
        #pragma unroll
        for (int r = 0; r < 4; r++) {
            int i  = tid + 128 * r;
            int kk = i >> 4;            // 0..31
            int nq = i & 15;            // 0..15
            *(float4*)&Ws[kk][nq * 4] = *(const float4*)&W[(size_t)(kt + kk) * 64 + nq * 4];
        }
        __syncthreads();
        #pragma unroll
        for (int kk = 0; kk < 32; kk++) {
            float av[4];
            #pragma unroll
            for (int i = 0; i < 4; i++) av[i] = As[kk][rowg * 4 + i];
            float4 w0 = *(const float4*)&Ws[kk][colg * 8];
            float4 w1 = *(const float4*)&Ws[kk][colg * 8 + 4];
            float wv[8] = {w0.x, w0.y, w0.z, w0.w, w1.x, w1.y, w1.z, w1.w};
            #pragma unroll
            for (int i = 0; i < 4; i++)
                #pragma unroll
                for (int j = 0; j < 8; j++)
                    acc[i][j] += av[i] * wv[j];
        }
        __syncthreads();
    }
    // epilogue: bias + relu
    #pragma unroll
    for (int i = 0; i < 4; i++) {
        int grow = row0 + rowg * 4 + i;
        if (grow < N_NODES) {
            #pragma unroll
            for (int j = 0; j < 8; j++) {
                int col = colg * 8 + j;
                float v = acc[i][j] + __ldg(&b[col]);
                out[(size_t)grow * F_OUT + col] = fmaxf(v, 0.0f);
            }
        }
    }
}

// ---------------------------------------------------------------------------
extern "C" void kernel_launch(void* const* d_in, const int* in_sizes, int n_in,
                              void* d_out, int out_size) {
    const float* x  = (const float*)d_in[0];
    const void*  ei = d_in[1];
    const float* W  = (const float*)d_in[2];
    const float* b  = (const float*)d_in[3];
    float*       out = (float*)d_out;

    detect_kernel<<<1, 32>>>((const unsigned int*)ei);
    zero_kernel<<<(N_NODES + 255) / 256, 256>>>();
    decode_hist_kernel<<<(N_EDGES + 255) / 256, 256>>>(ei);
    dis_kernel<<<(N_NODES + 255) / 256, 256>>>();
    scan_kernel<<<1, 1024>>>();
    scatter_kernel<<<(N_EDGES + 255) / 256, 256>>>();
    copyx_kernel<<<(N_NODES * F_IN + 255) / 256, 256>>>(x);

    // T1 = prop(T0)
    spmm_kernel<<<N_NODES, 128>>>(0, -1, 1, 0);
    // T_k = 2*prop(T_{k-1}) - T_{k-2}
    for (int k = 2; k < KORD; k++)
        spmm_kernel<<<N_NODES, 128>>>(k - 1, k - 2, k, 1);

    gemm_kernel<<<(N_NODES + 63) / 64, 128>>>(W, b, out);
}

// round 4
// speedup vs baseline: 1.8335x; 1.8335x over previous
#include <cuda_runtime.h>
#include <cuda_bf16.h>
#include <cstdint>

// ChebConv K=8 on GB300 (sm_103 base target — no tcgen05 in PTX):
//  - decode edges (dtype-robust), build CSR by dst (multi-block scan)
//  - 7 SpMM propagations: warp-per-node float4 gathers, emitting bf16 hi/lo panels
//  - GEMM [50000,1024]x[1024,64] via mma.sync bf16 split (AhiBhi+AhiBlo+AloBhi)
//    with pre-packed B fragments, + bias + ReLU

#define N_NODES 50000
#define N_EDGES 800000
#define F_IN    128
#define F_OUT   64
#define KORD    8
#define KTOT    (KORD * F_IN)          // 1024
#define NKSTEP  (KTOT / 16)            // 64
#define SCAN_BLK 1024
#define NBLK    ((N_NODES + SCAN_BLK - 1) / SCAN_BLK)   // 49
#define NWARPS_GEMM ((N_NODES + 31) / 32)               // 1563

// ---- scratch (static device globals; no allocations) ----
__device__ __align__(16) float         g_Tall[(size_t)N_NODES * KTOT];
__device__ __align__(16) __nv_bfloat16 g_Thi [(size_t)N_NODES * KTOT];
__device__ __align__(16) __nv_bfloat16 g_Tlo [(size_t)N_NODES * KTOT];
__device__ __align__(16) uint4         g_Wpack[NKSTEP * 8 * 32];  // fragment-packed W^T hi/lo
__device__ int   g_is64;
__device__ int   g_src[N_EDGES];
__device__ int   g_dst[N_EDGES];
__device__ int   g_cnt[N_NODES];
__device__ int   g_deg[N_NODES];
__device__ float g_dis[N_NODES];
__device__ int   g_rowptr[N_NODES + 1];
__device__ int   g_cursor[N_NODES];
__device__ int   g_bsum[NBLK];
__device__ int   g_boff[NBLK];
__device__ int   g_esrc[N_EDGES];
__device__ float g_ew[N_EDGES];

// =================== helpers ===============================================
__device__ __forceinline__ void mma16816(float* c, const uint32_t* a, const uint32_t* b) {
    asm volatile(
        "mma.sync.aligned.m16n8k16.row.col.f32.bf16.bf16.f32 "
        "{%0,%1,%2,%3}, {%4,%5,%6,%7}, {%8,%9}, {%0,%1,%2,%3};"
        : "+f"(c[0]), "+f"(c[1]), "+f"(c[2]), "+f"(c[3])
        : "r"(a[0]), "r"(a[1]), "r"(a[2]), "r"(a[3]), "r"(b[0]), "r"(b[1]));
}

__device__ __forceinline__ uint32_t pack_bf16x2(float a, float b) {
    __nv_bfloat16 ha = __float2bfloat16(a), hb = __float2bfloat16(b);
    return (uint32_t)__bfloat16_as_ushort(ha) |
           ((uint32_t)__bfloat16_as_ushort(hb) << 16);
}

// bf16 hi/lo split store of a float4 at element index o (same index in hi & lo)
__device__ __forceinline__ void store_hilo(size_t o, float4 r) {
    __nv_bfloat16 h0 = __float2bfloat16(r.x), h1 = __float2bfloat16(r.y);
    __nv_bfloat16 h2 = __float2bfloat16(r.z), h3 = __float2bfloat16(r.w);
    float l0 = r.x - __bfloat162float(h0), l1 = r.y - __bfloat162float(h1);
    float l2 = r.z - __bfloat162float(h2), l3 = r.w - __bfloat162float(h3);
    uint2 hv, lv;
    hv.x = (uint32_t)__bfloat16_as_ushort(h0) | ((uint32_t)__bfloat16_as_ushort(h1) << 16);
    hv.y = (uint32_t)__bfloat16_as_ushort(h2) | ((uint32_t)__bfloat16_as_ushort(h3) << 16);
    lv.x = pack_bf16x2(l0, l1);
    lv.y = pack_bf16x2(l2, l3);
    *(uint2*)&g_Thi[o] = hv;
    *(uint2*)&g_Tlo[o] = lv;
}

// ============================ preprocessing ================================
__global__ void detect_kernel(const unsigned int* __restrict__ p) {
    if (threadIdx.x == 0 && blockIdx.x == 0) {
        int is64 = 1;
        for (int i = 0; i < 256; i++)
            if (p[2 * i + 1] != 0u) { is64 = 0; break; }
        g_is64 = is64;
    }
}
__global__ void zero_kernel() {
    int i = blockIdx.x * blockDim.x + threadIdx.x;
    if (i < N_NODES) { g_cnt[i] = 0; g_deg[i] = 0; }
}
__global__ void decode_hist_kernel(const void* __restrict__ ei) {
    int e = blockIdx.x * blockDim.x + threadIdx.x;
    if (e < N_EDGES) {
        int s, d;
        if (g_is64) {
            const long long* p = (const long long*)ei;
            s = (int)p[e]; d = (int)p[N_EDGES + e];
        } else {
            const int* p = (const int*)ei;
            s = p[e]; d = p[N_EDGES + e];
        }
        s = min(max(s, 0), N_NODES - 1);
        d = min(max(d, 0), N_NODES - 1);
        g_src[e] = s; g_dst[e] = d;
        atomicAdd(&g_deg[s], 1);
        atomicAdd(&g_cnt[d], 1);
    }
}
__global__ void dis_kernel() {
    int i = blockIdx.x * blockDim.x + threadIdx.x;
    if (i < N_NODES) {
        int d = g_deg[i];
        g_dis[i] = (d > 0) ? rsqrtf((float)d) : 0.0f;
    }
}

// ---- 3-phase scan: cnt -> rowptr ----
__global__ void scan1_kernel() {
    __shared__ int wsum[32];
    int tid = threadIdx.x, lane = tid & 31, wid = tid >> 5;
    int i = blockIdx.x * SCAN_BLK + tid;
    int v = (i < N_NODES) ? g_cnt[i] : 0;
    int x = v;
    #pragma unroll
    for (int off = 1; off < 32; off <<= 1) {
        int t = __shfl_up_sync(0xffffffffu, x, off);
        if (lane >= off) x += t;
    }
    if (lane == 31) wsum[wid] = x;
    __syncthreads();
    if (wid == 0) {
        int y = wsum[lane];
        #pragma unroll
        for (int off = 1; off < 32; off <<= 1) {
            int t = __shfl_up_sync(0xffffffffu, y, off);
            if (lane >= off) y += t;
        }
        wsum[lane] = y;
    }
    __syncthreads();
    int excl = x - v + (wid > 0 ? wsum[wid - 1] : 0);
    if (i < N_NODES) g_rowptr[i] = excl;
    if (tid == 0) g_bsum[blockIdx.x] = wsum[31];
}
__global__ void scan2_kernel() {
    __shared__ int sh[64];
    int tid = threadIdx.x;
    int v = (tid < NBLK) ? g_bsum[tid] : 0;
    sh[tid] = v;
    __syncthreads();
    #pragma unroll
    for (int off = 1; off < 64; off <<= 1) {
        int t = (tid >= off) ? sh[tid - off] : 0;
        __syncthreads();
        sh[tid] += t;
        __syncthreads();
    }
    if (tid < NBLK) g_boff[tid] = sh[tid] - v;   // exclusive
}
__global__ void scan3_kernel() {
    int i = blockIdx.x * blockDim.x + threadIdx.x;
    if (i < N_NODES) {
        int val = g_rowptr[i] + g_boff[i >> 10];
        g_rowptr[i] = val;
        g_cursor[i] = val;
    }
    if (i == 0) g_rowptr[N_NODES] = N_EDGES;
}

__global__ void scatter_kernel() {
    int e = blockIdx.x * blockDim.x + threadIdx.x;
    if (e < N_EDGES) {
        int s = g_src[e];
        int d = g_dst[e];
        float w = -g_dis[s] * g_dis[d];
        int pos = atomicAdd(&g_cursor[d], 1);
        g_esrc[pos] = s;
        g_ew[pos]   = w;
    }
}

// pack W^T into mma B-fragment order: g_Wpack[(kstep*8+ntile)*32 + lane]
//   n  = ntile*8 + (lane>>2);  k0 = kstep*16 + (lane&3)*2
//   .x = hi{k0,k0+1}  .y = hi{k0+8,k0+9}  .z = lo{k0,k0+1}  .w = lo{k0+8,k0+9}
__global__ void packw_kernel(const float* __restrict__ W) {
    int i = blockIdx.x * blockDim.x + threadIdx.x;
    if (i >= NKSTEP * 8 * 32) return;
    int lane = i & 31, nt = (i >> 5) & 7, ks = i >> 8;
    int n  = nt * 8 + (lane >> 2);
    int k0 = ks * 16 + (lane & 3) * 2;
    float v00 = W[(size_t)(k0    ) * 64 + n];
    float v01 = W[(size_t)(k0 + 1) * 64 + n];
    float v10 = W[(size_t)(k0 + 8) * 64 + n];
    float v11 = W[(size_t)(k0 + 9) * 64 + n];
    __nv_bfloat16 h00 = __float2bfloat16(v00), h01 = __float2bfloat16(v01);
    __nv_bfloat16 h10 = __float2bfloat16(v10), h11 = __float2bfloat16(v11);
    uint4 p;
    p.x = (uint32_t)__bfloat16_as_ushort(h00) | ((uint32_t)__bfloat16_as_ushort(h01) << 16);
    p.y = (uint32_t)__bfloat16_as_ushort(h10) | ((uint32_t)__bfloat16_as_ushort(h11) << 16);
    p.z = pack_bf16x2(v00 - __bfloat162float(h00), v01 - __bfloat162float(h01));
    p.w = pack_bf16x2(v10 - __bfloat162float(h10), v11 - __bfloat162float(h11));
    g_Wpack[i] = p;
}

__global__ void copyx_kernel(const float* __restrict__ x) {
    int i = blockIdx.x * blockDim.x + threadIdx.x;   // float4 index
    if (i < N_NODES * (F_IN / 4)) {
        int row = i >> 5, c4 = i & 31;
        float4 v = __ldg((const float4*)x + i);
        size_t o = (size_t)row * KTOT + c4 * 4;      // slot 0
        *(float4*)&g_Tall[o] = v;
        store_hilo(o, v);
    }
}

// ============================== SpMM =======================================
// warp-per-node, 32 lanes x float4 = 128 features, 4-edge MLP
// mode 0: T_out = prop(T_in);  mode 1: T_out = 2*prop(T_in) - T_prev
__global__ void spmm_kernel(int slot_in, int slot_prev, int slot_out, int mode) {
    int warp = blockIdx.x * (blockDim.x >> 5) + (threadIdx.x >> 5);
    if (warp >= N_NODES) return;
    int lane = threadIdx.x & 31;
    int beg = g_rowptr[warp], end = g_rowptr[warp + 1];
    int cin = slot_in * F_IN;
    float4 acc = make_float4(0.f, 0.f, 0.f, 0.f);
    for (int e = beg; e < end; e += 4) {
        int e1 = min(e + 1, end - 1);
        int e2 = min(e + 2, end - 1);
        int e3 = min(e + 3, end - 1);
        int s0 = __ldg(&g_esrc[e]),  s1 = __ldg(&g_esrc[e1]);
        int s2 = __ldg(&g_esrc[e2]), s3 = __ldg(&g_esrc[e3]);
        float w0 = __ldg(&g_ew[e]);
        float w1 = (e + 1 < end) ? __ldg(&g_ew[e1]) : 0.f;
        float w2 = (e + 2 < end) ? __ldg(&g_ew[e2]) : 0.f;
        float w3 = (e + 3 < end) ? __ldg(&g_ew[e3]) : 0.f;
        float4 v0 = __ldg((const float4*)(g_Tall + (size_t)s0 * KTOT + cin) + lane);
        float4 v1 = __ldg((const float4*)(g_Tall + (size_t)s1 * KTOT + cin) + lane);
        float4 v2 = __ldg((const float4*)(g_Tall + (size_t)s2 * KTOT + cin) + lane);
        float4 v3 = __ldg((const float4*)(g_Tall + (size_t)s3 * KTOT + cin) + lane);
        acc.x += w0 * v0.x + w1 * v1.x + w2 * v2.x + w3 * v3.x;
        acc.y += w0 * v0.y + w1 * v1.y + w2 * v2.y + w3 * v3.y;
        acc.z += w0 * v0.z + w1 * v1.z + w2 * v2.z + w3 * v3.z;
        acc.w += w0 * v0.w + w1 * v1.w + w2 * v2.w + w3 * v3.w;
    }
    size_t obase = (size_t)warp * KTOT + slot_out * F_IN + lane * 4;
    float4 r = acc;
    if (mode) {
        float4 tp = *(const float4*)&g_Tall[(size_t)warp * KTOT + slot_prev * F_IN + lane * 4];
        r.x = 2.f * acc.x - tp.x; r.y = 2.f * acc.y - tp.y;
        r.z = 2.f * acc.z - tp.z; r.w = 2.f * acc.w - tp.w;
    }
    *(float4*)&g_Tall[obase] = r;
    store_hilo(obase, r);
}

// ============================== GEMM (mma.sync bf16 split) =================
// warp computes rows [warp*32, warp*32+32) x all 64 cols over K=1024.
// 2 M-tiles (16 rows) x 8 N-tiles (8 cols) per warp; 3 mma terms per tile pair.
__global__ void __launch_bounds__(128) gemm_mma_kernel(
        const float* __restrict__ bias, float* __restrict__ out) {
    int wid = threadIdx.x >> 5, lane = threadIdx.x & 31;
    int warp = blockIdx.x * 4 + wid;
    if (warp >= NWARPS_GEMM) return;
    int row0 = warp * 32;
    int r  = lane >> 2;
    int cc = (lane & 3) * 2;

    int rr[4];
    rr[0] = min(row0      + r, N_NODES - 1);
    rr[1] = min(row0 +  8 + r, N_NODES - 1);
    rr[2] = min(row0 + 16 + r, N_NODES - 1);
    rr[3] = min(row0 + 24 + r, N_NODES - 1);

    float acc[2][8][4];
    #pragma unroll
    for (int m = 0; m < 2; m++)
        #pragma unroll
        for (int j = 0; j < 8; j++)
            #pragma unroll
            for (int q = 0; q < 4; q++) acc[m][j][q] = 0.f;

    for (int ks = 0; ks < NKSTEP; ks++) {
        int kt = ks * 16;
        uint32_t ah[2][4], al[2][4];
        #pragma unroll
        for (int m = 0; m < 2; m++) {
            const __nv_bfloat16* h0 = g_Thi + (size_t)rr[2 * m    ] * KTOT + kt;
            const __nv_bfloat16* h1 = g_Thi + (size_t)rr[2 * m + 1] * KTOT + kt;
            const __nv_bfloat16* l0 = g_Tlo + (size_t)rr[2 * m    ] * KTOT + kt;
            const __nv_bfloat16* l1 = g_Tlo + (size_t)rr[2 * m + 1] * KTOT + kt;
            ah[m][0] = *(const uint32_t*)(h0 + cc);
            ah[m][1] = *(const uint32_t*)(h1 + cc);
            ah[m][2] = *(const uint32_t*)(h0 + cc + 8);
            ah[m][3] = *(const uint32_t*)(h1 + cc + 8);
            al[m][0] = *(const uint32_t*)(l0 + cc);
            al[m][1] = *(const uint32_t*)(l1 + cc);
            al[m][2] = *(const uint32_t*)(l0 + cc + 8);
            al[m][3] = *(const uint32_t*)(l1 + cc + 8);
        }
        const uint4* wp = g_Wpack + (size_t)ks * 8 * 32 + lane;
        #pragma unroll
        for (int j = 0; j < 8; j++) {
            uint4 bp = __ldg(wp + j * 32);
            uint32_t bh[2] = {bp.x, bp.y};
            uint32_t bl[2] = {bp.z, bp.w};
            mma16816(acc[0][j], ah[0], bh);
            mma16816(acc[0][j], ah[0], bl);
            mma16816(acc[0][j], al[0], bh);
            mma16816(acc[1][j], ah[1], bh);
            mma16816(acc[1][j], ah[1], bl);
            mma16816(acc[1][j], al[1], bh);
        }
    }

    // epilogue: bias + relu; C rows: row0+mt*16+r and +8; cols j*8+cc, +1
    #pragma unroll
    for (int m = 0; m < 2; m++) {
        int row_a = row0 + m * 16 + r;
        int row_b = row_a + 8;
        #pragma unroll
        for (int j = 0; j < 8; j++) {
            int col = j * 8 + cc;
            float b0 = __ldg(&bias[col]), b1 = __ldg(&bias[col + 1]);
            if (row_a < N_NODES) {
                float2 o;
                o.x = fmaxf(acc[m][j][0] + b0, 0.f);
                o.y = fmaxf(acc[m][j][1] + b1, 0.f);
                *(float2*)(out + (size_t)row_a * F_OUT + col) = o;
            }
            if (row_b < N_NODES) {
                float2 o;
                o.x = fmaxf(acc[m][j][2] + b0, 0.f);
                o.y = fmaxf(acc[m][j][3] + b1, 0.f);
                *(float2*)(out + (size_t)row_b * F_OUT + col) = o;
            }
        }
    }
}

// ---------------------------------------------------------------------------
extern "C" void kernel_launch(void* const* d_in, const int* in_sizes, int n_in,
                              void* d_out, int out_size) {
    const float* x  = (const float*)d_in[0];
    const void*  ei = d_in[1];
    const float* W  = (const float*)d_in[2];
    const float* b  = (const float*)d_in[3];
    float*       out = (float*)d_out;

    detect_kernel<<<1, 32>>>((const unsigned int*)ei);
    zero_kernel<<<(N_NODES + 255) / 256, 256>>>();
    decode_hist_kernel<<<(N_EDGES + 255) / 256, 256>>>(ei);
    dis_kernel<<<(N_NODES + 255) / 256, 256>>>();
    scan1_kernel<<<NBLK, SCAN_BLK>>>();
    scan2_kernel<<<1, 64>>>();
    scan3_kernel<<<(N_NODES + 255) / 256, 256>>>();
    scatter_kernel<<<(N_EDGES + 255) / 256, 256>>>();
    packw_kernel<<<(NKSTEP * 8 * 32 + 255) / 256, 256>>>(W);
    copyx_kernel<<<(N_NODES * (F_IN / 4) + 255) / 256, 256>>>(x);

    // T1 = prop(T0); T_k = 2*prop(T_{k-1}) - T_{k-2}
    spmm_kernel<<<(N_NODES + 7) / 8, 256>>>(0, -1, 1, 0);
    for (int k = 2; k < KORD; k++)
        spmm_kernel<<<(N_NODES + 7) / 8, 256>>>(k - 1, k - 2, k, 1);

    gemm_mma_kernel<<<(NWARPS_GEMM + 3) / 4, 128>>>(b, out);
}

// round 5
// speedup vs baseline: 2.1439x; 1.1693x over previous
#include <cuda_runtime.h>
#include <cuda_bf16.h>
#include <cstdint>

// ChebConv K=8 on GB300 (sm_103 base target — mma.sync tensor path):
//  - decode edges (dtype-robust), build padded CSR by dst
//  - 7 SpMM propagations over bf16 hi/lo panels (exact-split fp32 accuracy)
//  - GEMM [50000,1024]x[1024,64] via mma.sync bf16 split + bias + ReLU

#define N_NODES 50000
#define N_EDGES 800000
#define EPAD    (N_EDGES + 4 * N_NODES)      // padded edge capacity
#define F_IN    128
#define F_OUT   64
#define KORD    8
#define KTOT    (KORD * F_IN)                // 1024
#define NKSTEP  (KTOT / 16)                  // 64
#define SCAN_BLK 1024
#define NBLK    ((N_NODES + SCAN_BLK - 1) / SCAN_BLK)   // 49
#define NWARPS_GEMM ((N_NODES + 31) / 32)               // 1563

// ---- scratch (static device globals; no allocations) ----
__device__ __align__(16) __nv_bfloat16 g_Thi [(size_t)N_NODES * KTOT];
__device__ __align__(16) __nv_bfloat16 g_Tlo [(size_t)N_NODES * KTOT];
__device__ __align__(16) uint4         g_Wpack[NKSTEP * 8 * 32];
__device__ int   g_is64;
__device__ int   g_src[N_EDGES];
__device__ int   g_dst[N_EDGES];
__device__ int   g_cnt[N_NODES];
__device__ int   g_deg[N_NODES];
__device__ float g_dis[N_NODES];
__device__ int   g_rowptr[N_NODES + 1];      // padded CSR
__device__ int   g_cursor[N_NODES];
__device__ int   g_bsum[NBLK];
__device__ int   g_boff[NBLK];
__device__ __align__(8) int2 g_edge[EPAD];   // {src, float_bits(w)}

// =================== helpers ===============================================
__device__ __forceinline__ void mma16816(float* c, const uint32_t* a, const uint32_t* b) {
    asm volatile(
        "mma.sync.aligned.m16n8k16.row.col.f32.bf16.bf16.f32 "
        "{%0,%1,%2,%3}, {%4,%5,%6,%7}, {%8,%9}, {%0,%1,%2,%3};"
        : "+f"(c[0]), "+f"(c[1]), "+f"(c[2]), "+f"(c[3])
        : "r"(a[0]), "r"(a[1]), "r"(a[2]), "r"(a[3]), "r"(b[0]), "r"(b[1]));
}
__device__ __forceinline__ uint32_t pack_bf16x2(float a, float b) {
    __nv_bfloat16 ha = __float2bfloat16(a), hb = __float2bfloat16(b);
    return (uint32_t)__bfloat16_as_ushort(ha) |
           ((uint32_t)__bfloat16_as_ushort(hb) << 16);
}
// reconstruct 4 fp32 features from packed hi/lo bf16 pairs (2 ops per value)
__device__ __forceinline__ float4 unpack_hilo(uint2 h, uint2 l) {
    float4 v;
    v.x = __uint_as_float(h.x << 16)         + __uint_as_float(l.x << 16);
    v.y = __uint_as_float(h.x & 0xffff0000u) + __uint_as_float(l.x & 0xffff0000u);
    v.z = __uint_as_float(h.y << 16)         + __uint_as_float(l.y << 16);
    v.w = __uint_as_float(h.y & 0xffff0000u) + __uint_as_float(l.y & 0xffff0000u);
    return v;
}
// bf16 hi/lo split store of a float4 at element index o
__device__ __forceinline__ void store_hilo(size_t o, float4 r) {
    __nv_bfloat16 h0 = __float2bfloat16(r.x), h1 = __float2bfloat16(r.y);
    __nv_bfloat16 h2 = __float2bfloat16(r.z), h3 = __float2bfloat16(r.w);
    uint2 hv, lv;
    hv.x = (uint32_t)__bfloat16_as_ushort(h0) | ((uint32_t)__bfloat16_as_ushort(h1) << 16);
    hv.y = (uint32_t)__bfloat16_as_ushort(h2) | ((uint32_t)__bfloat16_as_ushort(h3) << 16);
    lv.x = pack_bf16x2(r.x - __bfloat162float(h0), r.y - __bfloat162float(h1));
    lv.y = pack_bf16x2(r.z - __bfloat162float(h2), r.w - __bfloat162float(h3));
    *(uint2*)&g_Thi[o] = hv;
    *(uint2*)&g_Tlo[o] = lv;
}

// ============================ preprocessing ================================
// detect dtype (block 0 / thread 0) + zero histograms
__global__ void init_kernel(const unsigned int* __restrict__ p) {
    int i = blockIdx.x * blockDim.x + threadIdx.x;
    if (i == 0) {
        int is64 = 1;
        for (int j = 0; j < 256; j++)
            if (p[2 * j + 1] != 0u) { is64 = 0; break; }
        g_is64 = is64;
    }
    if (i < N_NODES) { g_cnt[i] = 0; g_deg[i] = 0; }
}
__global__ void decode_hist_kernel(const void* __restrict__ ei) {
    int e = blockIdx.x * blockDim.x + threadIdx.x;
    if (e < N_EDGES) {
        int s, d;
        if (g_is64) {
            const long long* p = (const long long*)ei;
            s = (int)p[e]; d = (int)p[N_EDGES + e];
        } else {
            const int* p = (const int*)ei;
            s = p[e]; d = p[N_EDGES + e];
        }
        s = min(max(s, 0), N_NODES - 1);
        d = min(max(d, 0), N_NODES - 1);
        g_src[e] = s; g_dst[e] = d;
        atomicAdd(&g_deg[s], 1);
        atomicAdd(&g_cnt[d], 1);
    }
}
// scan over PADDED counts; also computes g_dis
__global__ void scan1_kernel() {
    __shared__ int wsum[32];
    int tid = threadIdx.x, lane = tid & 31, wid = tid >> 5;
    int i = blockIdx.x * SCAN_BLK + tid;
    int v = 0;
    if (i < N_NODES) {
        int d = g_deg[i];
        g_dis[i] = (d > 0) ? rsqrtf((float)d) : 0.0f;
        v = (g_cnt[i] + 3) & ~3;             // pad row to multiple of 4
    }
    int x = v;
    #pragma unroll
    for (int off = 1; off < 32; off <<= 1) {
        int t = __shfl_up_sync(0xffffffffu, x, off);
        if (lane >= off) x += t;
    }
    if (lane == 31) wsum[wid] = x;
    __syncthreads();
    if (wid == 0) {
        int y = wsum[lane];
        #pragma unroll
        for (int off = 1; off < 32; off <<= 1) {
            int t = __shfl_up_sync(0xffffffffu, y, off);
            if (lane >= off) y += t;
        }
        wsum[lane] = y;
    }
    __syncthreads();
    int excl = x - v + (wid > 0 ? wsum[wid - 1] : 0);
    if (i < N_NODES) g_rowptr[i] = excl;
    if (tid == 0) g_bsum[blockIdx.x] = wsum[31];
}
__global__ void scan2_kernel() {
    __shared__ int sh[64];
    int tid = threadIdx.x;
    int v = (tid < NBLK) ? g_bsum[tid] : 0;
    sh[tid] = v;
    __syncthreads();
    #pragma unroll
    for (int off = 1; off < 64; off <<= 1) {
        int t = (tid >= off) ? sh[tid - off] : 0;
        __syncthreads();
        sh[tid] += t;
        __syncthreads();
    }
    if (tid < NBLK) g_boff[tid] = sh[tid] - v;       // exclusive
    if (tid == NBLK - 1) g_rowptr[N_NODES] = sh[tid];
}
// finalize rowptr/cursor + pre-fill padding slots with {0, 0.0f}
__global__ void scan3_kernel() {
    int i = blockIdx.x * blockDim.x + threadIdx.x;
    if (i < N_NODES) {
        int val = g_rowptr[i] + g_boff[i >> 10];
        g_rowptr[i] = val;
        g_cursor[i] = val;
        int cnt  = g_cnt[i];
        int cntp = (cnt + 3) & ~3;
        for (int j = cnt; j < cntp; j++)
            g_edge[val + j] = make_int2(0, 0);
    }
}
__global__ void scatter_kernel() {
    int e = blockIdx.x * blockDim.x + threadIdx.x;
    if (e < N_EDGES) {
        int s = g_src[e];
        int d = g_dst[e];
        float w = -g_dis[s] * g_dis[d];
        int pos = atomicAdd(&g_cursor[d], 1);
        g_edge[pos] = make_int2(s, __float_as_int(w));
    }
}
// pack W^T into mma B-fragment order
__global__ void packw_kernel(const float* __restrict__ W) {
    int i = blockIdx.x * blockDim.x + threadIdx.x;
    if (i >= NKSTEP * 8 * 32) return;
    int lane = i & 31, nt = (i >> 5) & 7, ks = i >> 8;
    int n  = nt * 8 + (lane >> 2);
    int k0 = ks * 16 + (lane & 3) * 2;
    float v00 = W[(size_t)(k0    ) * 64 + n];
    float v01 = W[(size_t)(k0 + 1) * 64 + n];
    float v10 = W[(size_t)(k0 + 8) * 64 + n];
    float v11 = W[(size_t)(k0 + 9) * 64 + n];
    __nv_bfloat16 h00 = __float2bfloat16(v00), h01 = __float2bfloat16(v01);
    __nv_bfloat16 h10 = __float2bfloat16(v10), h11 = __float2bfloat16(v11);
    uint4 p;
    p.x = (uint32_t)__bfloat16_as_ushort(h00) | ((uint32_t)__bfloat16_as_ushort(h01) << 16);
    p.y = (uint32_t)__bfloat16_as_ushort(h10) | ((uint32_t)__bfloat16_as_ushort(h11) << 16);
    p.z = pack_bf16x2(v00 - __bfloat162float(h00), v01 - __bfloat162float(h01));
    p.w = pack_bf16x2(v10 - __bfloat162float(h10), v11 - __bfloat162float(h11));
    g_Wpack[i] = p;
}
__global__ void copyx_kernel(const float* __restrict__ x) {
    int i = blockIdx.x * blockDim.x + threadIdx.x;   // float4 index
    if (i < N_NODES * (F_IN / 4)) {
        int row = i >> 5, c4 = i & 31;
        float4 v = __ldg((const float4*)x + i);
        store_hilo((size_t)row * KTOT + c4 * 4, v);  // slot 0
    }
}

// ============================== SpMM =======================================
// warp-per-node, 32 lanes x 4 features; reads hi/lo panels, reconstructs fp32.
// rows padded to multiple of 4 (pad edges: src=0, w=0 -> L1-resident, free).
// mode 0: T_out = prop(T_in);  mode 1: T_out = 2*prop(T_in) - T_prev
__global__ void spmm_kernel(int slot_in, int slot_prev, int slot_out, int mode) {
    int warp = blockIdx.x * (blockDim.x >> 5) + (threadIdx.x >> 5);
    if (warp >= N_NODES) return;
    int lane = threadIdx.x & 31;
    int beg = g_rowptr[warp], end = g_rowptr[warp + 1];
    int cin = slot_in * F_IN;
    float4 acc = make_float4(0.f, 0.f, 0.f, 0.f);
    #pragma unroll 2
    for (int e = beg; e < end; e += 4) {
        int2 ed0 = __ldg(&g_edge[e]);
        int2 ed1 = __ldg(&g_edge[e + 1]);
        int2 ed2 = __ldg(&g_edge[e + 2]);
        int2 ed3 = __ldg(&g_edge[e + 3]);
        uint2 h0 = __ldg((const uint2*)(g_Thi + (size_t)ed0.x * KTOT + cin) + lane);
        uint2 l0 = __ldg((const uint2*)(g_Tlo + (size_t)ed0.x * KTOT + cin) + lane);
        uint2 h1 = __ldg((const uint2*)(g_Thi + (size_t)ed1.x * KTOT + cin) + lane);
        uint2 l1 = __ldg((const uint2*)(g_Tlo + (size_t)ed1.x * KTOT + cin) + lane);
        uint2 h2 = __ldg((const uint2*)(g_Thi + (size_t)ed2.x * KTOT + cin) + lane);
        uint2 l2 = __ldg((const uint2*)(g_Tlo + (size_t)ed2.x * KTOT + cin) + lane);
        uint2 h3 = __ldg((const uint2*)(g_Thi + (size_t)ed3.x * KTOT + cin) + lane);
        uint2 l3 = __ldg((const uint2*)(g_Tlo + (size_t)ed3.x * KTOT + cin) + lane);
        float w0 = __int_as_float(ed0.y), w1 = __int_as_float(ed1.y);
        float w2 = __int_as_float(ed2.y), w3 = __int_as_float(ed3.y);
        float4 v0 = unpack_hilo(h0, l0);
        float4 v1 = unpack_hilo(h1, l1);
        float4 v2 = unpack_hilo(h2, l2);
        float4 v3 = unpack_hilo(h3, l3);
        acc.x += w0 * v0.x + w1 * v1.x + w2 * v2.x + w3 * v3.x;
        acc.y += w0 * v0.y + w1 * v1.y + w2 * v2.y + w3 * v3.y;
        acc.z += w0 * v0.z + w1 * v1.z + w2 * v2.z + w3 * v3.z;
        acc.w += w0 * v0.w + w1 * v1.w + w2 * v2.w + w3 * v3.w;
    }
    size_t rbase = (size_t)warp * KTOT;
    float4 r = acc;
    if (mode) {
        size_t po = rbase + slot_prev * F_IN + lane * 4;
        float4 tp = unpack_hilo(*(const uint2*)&g_Thi[po], *(const uint2*)&g_Tlo[po]);
        r.x = 2.f * acc.x - tp.x; r.y = 2.f * acc.y - tp.y;
        r.z = 2.f * acc.z - tp.z; r.w = 2.f * acc.w - tp.w;
    }
    store_hilo(rbase + slot_out * F_IN + lane * 4, r);
}

// ============================== GEMM (mma.sync bf16 split) =================
__global__ void __launch_bounds__(128) gemm_mma_kernel(
        const float* __restrict__ bias, float* __restrict__ out) {
    int wid = threadIdx.x >> 5, lane = threadIdx.x & 31;
    int warp = blockIdx.x * 4 + wid;
    if (warp >= NWARPS_GEMM) return;
    int row0 = warp * 32;
    int r  = lane >> 2;
    int cc = (lane & 3) * 2;

    int rr[4];
    rr[0] = min(row0      + r, N_NODES - 1);
    rr[1] = min(row0 +  8 + r, N_NODES - 1);
    rr[2] = min(row0 + 16 + r, N_NODES - 1);
    rr[3] = min(row0 + 24 + r, N_NODES - 1);

    float acc[2][8][4];
    #pragma unroll
    for (int m = 0; m < 2; m++)
        #pragma unroll
        for (int j = 0; j < 8; j++)
            #pragma unroll
            for (int q = 0; q < 4; q++) acc[m][j][q] = 0.f;

    for (int ks = 0; ks < NKSTEP; ks++) {
        int kt = ks * 16;
        uint32_t ah[2][4], al[2][4];
        #pragma unroll
        for (int m = 0; m < 2; m++) {
            const __nv_bfloat16* h0 = g_Thi + (size_t)rr[2 * m    ] * KTOT + kt;
            const __nv_bfloat16* h1 = g_Thi + (size_t)rr[2 * m + 1] * KTOT + kt;
            const __nv_bfloat16* l0 = g_Tlo + (size_t)rr[2 * m    ] * KTOT + kt;
            const __nv_bfloat16* l1 = g_Tlo + (size_t)rr[2 * m + 1] * KTOT + kt;
            ah[m][0] = *(const uint32_t*)(h0 + cc);
            ah[m][1] = *(const uint32_t*)(h1 + cc);
            ah[m][2] = *(const uint32_t*)(h0 + cc + 8);
            ah[m][3] = *(const uint32_t*)(h1 + cc + 8);
            al[m][0] = *(const uint32_t*)(l0 + cc);
            al[m][1] = *(const uint32_t*)(l1 + cc);
            al[m][2] = *(const uint32_t*)(l0 + cc + 8);
            al[m][3] = *(const uint32_t*)(l1 + cc + 8);
        }
        const uint4* wp = g_Wpack + (size_t)ks * 8 * 32 + lane;
        #pragma unroll
        for (int j = 0; j < 8; j++) {
            uint4 bp = __ldg(wp + j * 32);
            uint32_t bh[2] = {bp.x, bp.y};
            uint32_t bl[2] = {bp.z, bp.w};
            mma16816(acc[0][j], ah[0], bh);
            mma16816(acc[0][j], ah[0], bl);
            mma16816(acc[0][j], al[0], bh);
            mma16816(acc[1][j], ah[1], bh);
            mma16816(acc[1][j], ah[1], bl);
            mma16816(acc[1][j], al[1], bh);
        }
    }

    #pragma unroll
    for (int m = 0; m < 2; m++) {
        int row_a = row0 + m * 16 + r;
        int row_b = row_a + 8;
        #pragma unroll
        for (int j = 0; j < 8; j++) {
            int col = j * 8 + cc;
            float b0 = __ldg(&bias[col]), b1 = __ldg(&bias[col + 1]);
            if (row_a < N_NODES) {
                float2 o;
                o.x = fmaxf(acc[m][j][0] + b0, 0.f);
                o.y = fmaxf(acc[m][j][1] + b1, 0.f);
                *(float2*)(out + (size_t)row_a * F_OUT + col) = o;
            }
            if (row_b < N_NODES) {
                float2 o;
                o.x = fmaxf(acc[m][j][2] + b0, 0.f);
                o.y = fmaxf(acc[m][j][3] + b1, 0.f);
                *(float2*)(out + (size_t)row_b * F_OUT + col) = o;
            }
        }
    }
}

// ---------------------------------------------------------------------------
extern "C" void kernel_launch(void* const* d_in, const int* in_sizes, int n_in,
                              void* d_out, int out_size) {
    const float* x  = (const float*)d_in[0];
    const void*  ei = d_in[1];
    const float* W  = (const float*)d_in[2];
    const float* b  = (const float*)d_in[3];
    float*       out = (float*)d_out;

    init_kernel<<<(N_NODES + 255) / 256, 256>>>((const unsigned int*)ei);
    decode_hist_kernel<<<(N_EDGES + 255) / 256, 256>>>(ei);
    scan1_kernel<<<NBLK, SCAN_BLK>>>();
    scan2_kernel<<<1, 64>>>();
    scan3_kernel<<<(N_NODES + 255) / 256, 256>>>();
    scatter_kernel<<<(N_EDGES + 255) / 256, 256>>>();
    packw_kernel<<<(NKSTEP * 8 * 32 + 255) / 256, 256>>>(W);
    copyx_kernel<<<(N_NODES * (F_IN / 4) + 255) / 256, 256>>>(x);

    // T1 = prop(T0); T_k = 2*prop(T_{k-1}) - T_{k-2}
    spmm_kernel<<<(N_NODES + 7) / 8, 256>>>(0, -1, 1, 0);
    for (int k = 2; k < KORD; k++)
        spmm_kernel<<<(N_NODES + 7) / 8, 256>>>(k - 1, k - 2, k, 1);

    gemm_mma_kernel<<<(NWARPS_GEMM + 3) / 4, 128>>>(b, out);
}